// round 1
// baseline (speedup 1.0000x reference)
#include <cuda_runtime.h>
#include <cuda_bf16.h>
#include <cstdint>

// Problem constants
#define BATCH 2
#define SEQ   2048
#define EMB   1024
#define HEADS 16
#define HDIM  64
#define BH    (BATCH*HEADS)
#define ROWS  (BATCH*SEQ)     // 4096

// ---------------- scratch (device globals; no allocation allowed) ----------
__device__ float g_q[BH * HDIM * SEQ];     // [bh][d][s]  d-major
__device__ float g_k[BH * HDIM * SEQ];     // [bh][d][s]
__device__ float g_v[BH * SEQ * HDIM];     // [bh][s][d]
__device__ float g_attn[ROWS * EMB];       // [b*S+s][h*64+d] natural

// ---------------- GEMM: Y = X @ W^T + bias, fp32, NT ----------------------
// X: [4096,1024] row-major, W: [1024,1024] row-major (row n = output feature)
// layout 0: Y[m][n] natural
// layout 1: Y[((b*16+h)*64+d)*2048 + s]   (d-major per head; for Q,K)
// layout 2: Y[((b*16+h)*2048+s)*64 + d]   (s-major per head; for V)
#define GBM 128
#define GBN 128
#define GBK 16

__global__ __launch_bounds__(256) void gemm_nt(
    const float* __restrict__ X, const float* __restrict__ W,
    const float* __restrict__ bias, float* __restrict__ Y, int layout)
{
    __shared__ float Xs[GBK][GBM];
    __shared__ float Ws[GBK][GBN];

    const int tid = threadIdx.x;
    const int tx = tid & 15;          // 0..15 -> n micro
    const int ty = tid >> 4;          // 0..15 -> m micro
    const int m0 = blockIdx.y * GBM;
    const int n0 = blockIdx.x * GBN;

    float acc[8][8];
#pragma unroll
    for (int r = 0; r < 8; ++r)
#pragma unroll
        for (int c = 0; c < 8; ++c) acc[r][c] = 0.f;

    for (int k0 = 0; k0 < EMB; k0 += GBK) {
        // load tiles (transposed into smem): 512 float4 each, 2 per thread
#pragma unroll
        for (int t = 0; t < 2; ++t) {
            int v = tid + t * 256;
            int row = v >> 2;
            int kq  = (v & 3) * 4;
            float4 xv = *reinterpret_cast<const float4*>(&X[(size_t)(m0 + row) * EMB + k0 + kq]);
            Xs[kq + 0][row] = xv.x; Xs[kq + 1][row] = xv.y;
            Xs[kq + 2][row] = xv.z; Xs[kq + 3][row] = xv.w;
            float4 wv = *reinterpret_cast<const float4*>(&W[(size_t)(n0 + row) * EMB + k0 + kq]);
            Ws[kq + 0][row] = wv.x; Ws[kq + 1][row] = wv.y;
            Ws[kq + 2][row] = wv.z; Ws[kq + 3][row] = wv.w;
        }
        __syncthreads();

#pragma unroll
        for (int k = 0; k < GBK; ++k) {
            float a[8], b[8];
            *reinterpret_cast<float4*>(&a[0]) = *reinterpret_cast<float4*>(&Xs[k][ty * 8]);
            *reinterpret_cast<float4*>(&a[4]) = *reinterpret_cast<float4*>(&Xs[k][ty * 8 + 4]);
            *reinterpret_cast<float4*>(&b[0]) = *reinterpret_cast<float4*>(&Ws[k][tx * 8]);
            *reinterpret_cast<float4*>(&b[4]) = *reinterpret_cast<float4*>(&Ws[k][tx * 8 + 4]);
#pragma unroll
            for (int r = 0; r < 8; ++r)
#pragma unroll
                for (int c = 0; c < 8; ++c) acc[r][c] = fmaf(a[r], b[c], acc[r][c]);
        }
        __syncthreads();
    }

    // bias
    float bi[8];
    *reinterpret_cast<float4*>(&bi[0]) = *reinterpret_cast<const float4*>(&bias[n0 + tx * 8]);
    *reinterpret_cast<float4*>(&bi[4]) = *reinterpret_cast<const float4*>(&bias[n0 + tx * 8 + 4]);

    if (layout == 0) {
#pragma unroll
        for (int r = 0; r < 8; ++r) {
            int m = m0 + ty * 8 + r;
            float4 v0 = make_float4(acc[r][0] + bi[0], acc[r][1] + bi[1],
                                    acc[r][2] + bi[2], acc[r][3] + bi[3]);
            float4 v1 = make_float4(acc[r][4] + bi[4], acc[r][5] + bi[5],
                                    acc[r][6] + bi[6], acc[r][7] + bi[7]);
            *reinterpret_cast<float4*>(&Y[(size_t)m * EMB + n0 + tx * 8])     = v0;
            *reinterpret_cast<float4*>(&Y[(size_t)m * EMB + n0 + tx * 8 + 4]) = v1;
        }
    } else if (layout == 1) {
        // d-major per head: contiguous along s (= m)
        int bI = m0 >> 11;
        int sB = (m0 & 2047) + ty * 8;
#pragma unroll
        for (int c = 0; c < 8; ++c) {
            int n = n0 + tx * 8 + c;
            int h = n >> 6, d = n & 63;
            size_t base = ((size_t)(bI * HEADS + h) * HDIM + d) * SEQ + sB;
            float4 v0 = make_float4(acc[0][c] + bi[c], acc[1][c] + bi[c],
                                    acc[2][c] + bi[c], acc[3][c] + bi[c]);
            float4 v1 = make_float4(acc[4][c] + bi[c], acc[5][c] + bi[c],
                                    acc[6][c] + bi[c], acc[7][c] + bi[c]);
            *reinterpret_cast<float4*>(&Y[base])     = v0;
            *reinterpret_cast<float4*>(&Y[base + 4]) = v1;
        }
    } else {
        // layout 2: per-head s-major [bh][s][d]; contiguous along d (= n)
        int nb = n0 + tx * 8;
        int h = nb >> 6, d0 = nb & 63;   // c=0..7 stays within one head
#pragma unroll
        for (int r = 0; r < 8; ++r) {
            int m = m0 + ty * 8 + r;
            int bI = m >> 11, sI = m & 2047;
            size_t base = ((size_t)(bI * HEADS + h) * SEQ + sI) * HDIM + d0;
            float4 v0 = make_float4(acc[r][0] + bi[0], acc[r][1] + bi[1],
                                    acc[r][2] + bi[2], acc[r][3] + bi[3]);
            float4 v1 = make_float4(acc[r][4] + bi[4], acc[r][5] + bi[5],
                                    acc[r][6] + bi[6], acc[r][7] + bi[7]);
            *reinterpret_cast<float4*>(&Y[base])     = v0;
            *reinterpret_cast<float4*>(&Y[base + 4]) = v1;
        }
    }
}

// ---------------- flash attention, fp32 -----------------------------------
// grid: (S/128, BH); block 256 (16x16). Each thread: 8 query rows x 4 cols.
#define ABM 128
#define ABN 64
#define PS_STRIDE 68   // padded, 16B-aligned rows

__device__ __forceinline__ float red_max16(float v) {
    v = fmaxf(v, __shfl_xor_sync(0xffffffffu, v, 1));
    v = fmaxf(v, __shfl_xor_sync(0xffffffffu, v, 2));
    v = fmaxf(v, __shfl_xor_sync(0xffffffffu, v, 4));
    v = fmaxf(v, __shfl_xor_sync(0xffffffffu, v, 8));
    return v;
}
__device__ __forceinline__ float red_sum16(float v) {
    v += __shfl_xor_sync(0xffffffffu, v, 1);
    v += __shfl_xor_sync(0xffffffffu, v, 2);
    v += __shfl_xor_sync(0xffffffffu, v, 4);
    v += __shfl_xor_sync(0xffffffffu, v, 8);
    return v;
}

#define ATTN_SMEM ((HDIM*ABM + HDIM*ABN + ABN*HDIM + ABM*PS_STRIDE) * 4)

__global__ __launch_bounds__(256, 2) void attn_kernel(
    const float* __restrict__ Qd, const float* __restrict__ Kd,
    const float* __restrict__ Vn, const float* __restrict__ adj,
    const int* __restrict__ mask, float* __restrict__ out)
{
    extern __shared__ float sm[];
    float* Qs = sm;                          // [64][128] d-major
    float* Ks = Qs + HDIM * ABM;             // [64][64]  d-major
    float* Vs = Ks + HDIM * ABN;             // [64][64]  j-major
    float* Ps = Vs + ABN * HDIM;             // [128][68]

    const int tid = threadIdx.x;
    const int tx = tid & 15;
    const int ty = tid >> 4;
    const int bh = blockIdx.y;
    const int b  = bh >> 4;
    const int h  = bh & 15;
    const int q0 = blockIdx.x * ABM;

    // load Q tile: Qd[(bh*64+d)*2048 + q0+i] -> Qs[d][i]; 2048 float4, 8/thread
#pragma unroll
    for (int t = 0; t < 8; ++t) {
        int v = tid + t * 256;
        int d = v >> 5;
        int i4 = (v & 31) * 4;
        *reinterpret_cast<float4*>(&Qs[d * ABM + i4]) =
            *reinterpret_cast<const float4*>(&Qd[((size_t)bh * HDIM + d) * SEQ + q0 + i4]);
    }

    float o[8][4];
    float mrun[8], lrun[8];
#pragma unroll
    for (int r = 0; r < 8; ++r) {
        mrun[r] = -1e30f; lrun[r] = 0.f;
#pragma unroll
        for (int c = 0; c < 4; ++c) o[r][c] = 0.f;
    }

    for (int kt = 0; kt < SEQ / ABN; ++kt) {
        int k0 = kt * ABN;
        // load K,V tiles: 1024 float4 each, 4/thread
#pragma unroll
        for (int t = 0; t < 4; ++t) {
            int v = tid + t * 256;
            int row = v >> 4;
            int c4 = (v & 15) * 4;
            *reinterpret_cast<float4*>(&Ks[row * ABN + c4]) =
                *reinterpret_cast<const float4*>(&Kd[((size_t)bh * HDIM + row) * SEQ + k0 + c4]);
            *reinterpret_cast<float4*>(&Vs[row * HDIM + c4]) =
                *reinterpret_cast<const float4*>(&Vn[((size_t)bh * SEQ + k0 + row) * HDIM + c4]);
        }
        __syncthreads();

        // S = Q @ K^T
        float sacc[8][4];
#pragma unroll
        for (int r = 0; r < 8; ++r)
#pragma unroll
            for (int c = 0; c < 4; ++c) sacc[r][c] = 0.f;

#pragma unroll 8
        for (int d = 0; d < HDIM; ++d) {
            float a[8], bb[4];
            *reinterpret_cast<float4*>(&a[0]) = *reinterpret_cast<float4*>(&Qs[d * ABM + ty * 8]);
            *reinterpret_cast<float4*>(&a[4]) = *reinterpret_cast<float4*>(&Qs[d * ABM + ty * 8 + 4]);
            *reinterpret_cast<float4*>(&bb[0]) = *reinterpret_cast<float4*>(&Ks[d * ABN + tx * 4]);
#pragma unroll
            for (int r = 0; r < 8; ++r)
#pragma unroll
                for (int c = 0; c < 4; ++c) sacc[r][c] = fmaf(a[r], bb[c], sacc[r][c]);
        }

        // online softmax epilogue
#pragma unroll
        for (int r = 0; r < 8; ++r) {
            int iq = q0 + ty * 8 + r;
            float4 ad = *reinterpret_cast<const float4*>(&adj[(size_t)iq * SEQ + k0 + tx * 4]);
            int4 mk = *reinterpret_cast<const int4*>(&mask[((size_t)b * SEQ + iq) * SEQ + k0 + tx * 4]);
            float sc0 = fmaf(sacc[r][0], 0.125f, ad.x);
            float sc1 = fmaf(sacc[r][1], 0.125f, ad.y);
            float sc2 = fmaf(sacc[r][2], 0.125f, ad.z);
            float sc3 = fmaf(sacc[r][3], 0.125f, ad.w);
            float c0 = (mk.x != 0) ? sc0 : -1e30f;
            float c1 = (mk.y != 0) ? sc1 : -1e30f;
            float c2 = (mk.z != 0) ? sc2 : -1e30f;
            float c3 = (mk.w != 0) ? sc3 : -1e30f;
            float mt = red_max16(fmaxf(fmaxf(c0, c1), fmaxf(c2, c3)));
            float mn = fmaxf(mrun[r], mt);
            float p0 = (mk.x != 0) ? __expf(sc0 - mn) : 0.f;
            float p1 = (mk.y != 0) ? __expf(sc1 - mn) : 0.f;
            float p2 = (mk.z != 0) ? __expf(sc2 - mn) : 0.f;
            float p3 = (mk.w != 0) ? __expf(sc3 - mn) : 0.f;
            float rs = red_sum16(p0 + p1 + p2 + p3);
            float sca = __expf(mrun[r] - mn);
            lrun[r] = lrun[r] * sca + rs;
            mrun[r] = mn;
            o[r][0] *= sca; o[r][1] *= sca; o[r][2] *= sca; o[r][3] *= sca;
            *reinterpret_cast<float4*>(&Ps[(ty * 8 + r) * PS_STRIDE + tx * 4]) =
                make_float4(p0, p1, p2, p3);
        }
        __syncwarp();   // P rows are produced and consumed within the same warp

        // O += P @ V
#pragma unroll 4
        for (int j4 = 0; j4 < ABN / 4; ++j4) {
            float pr[8][4];
#pragma unroll
            for (int r = 0; r < 8; ++r)
                *reinterpret_cast<float4*>(&pr[r][0]) =
                    *reinterpret_cast<float4*>(&Ps[(ty * 8 + r) * PS_STRIDE + j4 * 4]);
#pragma unroll
            for (int u = 0; u < 4; ++u) {
                float bb[4];
                *reinterpret_cast<float4*>(&bb[0]) =
                    *reinterpret_cast<float4*>(&Vs[(j4 * 4 + u) * HDIM + tx * 4]);
#pragma unroll
                for (int r = 0; r < 8; ++r)
#pragma unroll
                    for (int c = 0; c < 4; ++c) o[r][c] = fmaf(pr[r][u], bb[c], o[r][c]);
            }
        }
        __syncthreads();   // protect Ks/Vs before next tile load
    }

    // normalize + write [b][s][h*64+d]
#pragma unroll
    for (int r = 0; r < 8; ++r) {
        float inv = 1.0f / lrun[r];
        int iq = q0 + ty * 8 + r;
        float4 v = make_float4(o[r][0] * inv, o[r][1] * inv, o[r][2] * inv, o[r][3] * inv);
        *reinterpret_cast<float4*>(&out[((size_t)b * SEQ + iq) * EMB + h * HDIM + tx * 4]) = v;
    }
}

// ---------------- launch ---------------------------------------------------
extern "C" void kernel_launch(void* const* d_in, const int* in_sizes, int n_in,
                              void* d_out, int out_size)
{
    const float* query = (const float*)d_in[0];
    const float* key   = (const float*)d_in[1];
    const float* value = (const float*)d_in[2];
    const float* adj   = (const float*)d_in[3];
    const int*   mask  = (const int*)d_in[4];
    const float* Wq = (const float*)d_in[5];
    const float* bq = (const float*)d_in[6];
    const float* Wk = (const float*)d_in[7];
    const float* bk = (const float*)d_in[8];
    const float* Wv = (const float*)d_in[9];
    const float* bv = (const float*)d_in[10];
    const float* Wo = (const float*)d_in[11];
    const float* bo = (const float*)d_in[12];
    float* out = (float*)d_out;

    float *gq, *gk, *gv, *ga;
    cudaGetSymbolAddress((void**)&gq, g_q);
    cudaGetSymbolAddress((void**)&gk, g_k);
    cudaGetSymbolAddress((void**)&gv, g_v);
    cudaGetSymbolAddress((void**)&ga, g_attn);

    cudaFuncSetAttribute(attn_kernel, cudaFuncAttributeMaxDynamicSharedMemorySize, ATTN_SMEM);

    dim3 ggrid(EMB / GBN, ROWS / GBM);   // (8, 32)
    gemm_nt<<<ggrid, 256>>>(query, Wq, bq, gq, 1);
    gemm_nt<<<ggrid, 256>>>(key,   Wk, bk, gk, 1);
    gemm_nt<<<ggrid, 256>>>(value, Wv, bv, gv, 2);

    dim3 agrid(SEQ / ABM, BH);           // (16, 32)
    attn_kernel<<<agrid, 256, ATTN_SMEM>>>(gq, gk, gv, adj, mask, ga);

    gemm_nt<<<ggrid, 256>>>(ga, Wo, bo, out, 0);
}

// round 2
// speedup vs baseline: 2.5345x; 2.5345x over previous
#include <cuda_runtime.h>
#include <cstdint>

#define BATCH 2
#define SEQ   2048
#define EMB   1024
#define HEADS 16
#define HDIM  64
#define BH    (BATCH*HEADS)
#define ROWS  (BATCH*SEQ)

// ---------------- scratch (tf32 bits stored in float arrays) --------------
__device__ float g_q[BH * SEQ * HDIM];   // [bh][s][d]  tf32 bits, pre-scaled 1/8
__device__ float g_k[BH * SEQ * HDIM];   // [bh][s][d]  tf32 bits
__device__ float g_v[BH * HDIM * SEQ];   // [bh][d][s]  tf32 bits
__device__ float g_attn[ROWS * EMB];     // fp32 natural

// ---------------- helpers -------------------------------------------------
__device__ __forceinline__ uint32_t f2tf(float x) {
    uint32_t r;
    asm("cvt.rna.tf32.f32 %0, %1;" : "=r"(r) : "f"(x));
    return r;
}

__device__ __forceinline__ void mma8(float* d, const uint32_t* a, uint32_t b0, uint32_t b1) {
    asm volatile(
        "mma.sync.aligned.m16n8k8.row.col.f32.tf32.tf32.f32 "
        "{%0,%1,%2,%3}, {%4,%5,%6,%7}, {%8,%9}, {%0,%1,%2,%3};"
        : "+f"(d[0]), "+f"(d[1]), "+f"(d[2]), "+f"(d[3])
        : "r"(a[0]), "r"(a[1]), "r"(a[2]), "r"(a[3]), "r"(b0), "r"(b1));
}

// ---------------- GEMM: Y = (X @ W^T + b) * scale, tf32 mma ---------------
// X:[4096,1024] W:[1024,1024] row-major (NT). 128x128x32 tile, 4 warps,
// warp tile 64x64 (4 mt x 8 nt of m16n8k8).
// layout 0: fp32 natural [m][n]
// layout 1: tf32 bits, V layout [bh][d][s]
// layout 2: tf32 bits, Q/K layout [bh][s][d]
__global__ __launch_bounds__(128, 2) void gemm_tf32(
    const float* __restrict__ X, const float* __restrict__ W,
    const float* __restrict__ bias, float* __restrict__ Y,
    int layout, float scale)
{
    __shared__ uint32_t As[128 * 32];
    __shared__ uint32_t Ws[128 * 32];

    const int tid = threadIdx.x;
    const int lane = tid & 31;
    const int wid = tid >> 5;
    const int wm = (wid & 1) * 64;
    const int wn = (wid >> 1) * 64;
    const int g = lane >> 2;   // 0..7
    const int j = lane & 3;    // 0..3
    const int m0 = blockIdx.y * 128;
    const int n0 = blockIdx.x * 128;

    float acc[4][8][4];
#pragma unroll
    for (int mt = 0; mt < 4; ++mt)
#pragma unroll
        for (int nt = 0; nt < 8; ++nt)
#pragma unroll
            for (int c = 0; c < 4; ++c) acc[mt][nt][c] = 0.f;

    for (int k0 = 0; k0 < EMB; k0 += 32) {
        // load + cvt + swizzled store: phys float4 slot = c ^ (row&7)
#pragma unroll
        for (int i = 0; i < 8; ++i) {
            int v = tid + i * 128;
            int row = v >> 3, c = v & 7;
            uint32_t ph = (uint32_t)(row * 32 + ((c ^ (row & 7)) << 2));
            float4 xv = *reinterpret_cast<const float4*>(&X[(size_t)(m0 + row) * EMB + k0 + c * 4]);
            *reinterpret_cast<uint4*>(&As[ph]) =
                make_uint4(f2tf(xv.x), f2tf(xv.y), f2tf(xv.z), f2tf(xv.w));
            float4 wv = *reinterpret_cast<const float4*>(&W[(size_t)(n0 + row) * EMB + k0 + c * 4]);
            *reinterpret_cast<uint4*>(&Ws[ph]) =
                make_uint4(f2tf(wv.x), f2tf(wv.y), f2tf(wv.z), f2tf(wv.w));
        }
        __syncthreads();

#pragma unroll
        for (int ks = 0; ks < 4; ++ks) {
            const int c0 = ((2 * ks) ^ g) << 2;
            const int c1 = ((2 * ks + 1) ^ g) << 2;
            uint32_t a[4][4];
#pragma unroll
            for (int mt = 0; mt < 4; ++mt) {
                int m = wm + mt * 16 + g;
                a[mt][0] = As[m * 32 + c0 + j];
                a[mt][2] = As[m * 32 + c1 + j];
                a[mt][1] = As[(m + 8) * 32 + c0 + j];
                a[mt][3] = As[(m + 8) * 32 + c1 + j];
            }
#pragma unroll
            for (int nt = 0; nt < 8; ++nt) {
                int n = wn + nt * 8 + g;
                uint32_t b0 = Ws[n * 32 + c0 + j];
                uint32_t b1 = Ws[n * 32 + c1 + j];
#pragma unroll
                for (int mt = 0; mt < 4; ++mt) mma8(acc[mt][nt], a[mt], b0, b1);
            }
        }
        __syncthreads();
    }

    // epilogue
    uint32_t* Yu = reinterpret_cast<uint32_t*>(Y);
#pragma unroll
    for (int nt = 0; nt < 8; ++nt) {
        int n = n0 + wn + nt * 8 + 2 * j;
        float2 bb = *reinterpret_cast<const float2*>(&bias[n]);
#pragma unroll
        for (int mt = 0; mt < 4; ++mt) {
            int m = m0 + wm + mt * 16 + g;
            float v00 = (acc[mt][nt][0] + bb.x) * scale;
            float v01 = (acc[mt][nt][1] + bb.y) * scale;
            float v10 = (acc[mt][nt][2] + bb.x) * scale;
            float v11 = (acc[mt][nt][3] + bb.y) * scale;
            if (layout == 0) {
                *reinterpret_cast<float2*>(&Y[(size_t)m * EMB + n]) = make_float2(v00, v01);
                *reinterpret_cast<float2*>(&Y[(size_t)(m + 8) * EMB + n]) = make_float2(v10, v11);
            } else {
                int bI = m >> 11, s = m & 2047;
                int h = n >> 6, d = n & 63;
                if (layout == 2) {  // [bh][s][d]
                    size_t base = ((size_t)(bI * HEADS + h) * SEQ + s) * HDIM + d;
                    *reinterpret_cast<uint2*>(&Yu[base]) = make_uint2(f2tf(v00), f2tf(v01));
                    *reinterpret_cast<uint2*>(&Yu[base + 8 * HDIM]) = make_uint2(f2tf(v10), f2tf(v11));
                } else {            // layout 1: [bh][d][s]
                    size_t base = ((size_t)(bI * HEADS + h) * HDIM + d) * SEQ + s;
                    Yu[base] = f2tf(v00);
                    Yu[base + SEQ] = f2tf(v01);
                    Yu[base + 8] = f2tf(v10);
                    Yu[base + SEQ + 8] = f2tf(v11);
                }
            }
        }
    }
}

// ---------------- flash attention, tf32 mma --------------------------------
// block 256 thr = 8 warps; warp w owns q rows [q0+w*16, +16).
// Q tile 128x64 (persistent), K/V tiles 64x64 per iter, P per-warp private.
#define ATTN_WORDS (128*64 + 64*64 + 64*64 + 128*64)
#define ATTN_SMEM  (ATTN_WORDS * 4)

__global__ __launch_bounds__(256, 2) void attn_tf32(
    const float* __restrict__ Qg, const float* __restrict__ Kg,
    const float* __restrict__ Vg, const float* __restrict__ adj,
    const int* __restrict__ mask, float* __restrict__ outp)
{
    extern __shared__ uint32_t smw[];
    uint32_t* Qs = smw;             // [128][64] swizzled
    uint32_t* Ks = Qs + 128 * 64;   // [key64][d64]
    uint32_t* Vs = Ks + 64 * 64;    // [d64][key64]
    uint32_t* Ps = Vs + 64 * 64;    // [128][key64]

    const int tid = threadIdx.x;
    const int lane = tid & 31;
    const int w = tid >> 5;
    const int g = lane >> 2, j = lane & 3;
    const int bh = blockIdx.y;
    const int b = bh >> 4, h = bh & 15;
    const int q0 = blockIdx.x * 128;

    // load Q tile (tf32 bits already)
    const uint4* Qgv = reinterpret_cast<const uint4*>(Qg + ((size_t)bh * SEQ + q0) * HDIM);
#pragma unroll
    for (int i = 0; i < 8; ++i) {
        int v = tid + i * 256;
        int row = v >> 4, idx = v & 15;
        uint32_t ph = row * 64 + ((idx >> 3) << 5) + (((idx & 7) ^ (row & 7)) << 2);
        *reinterpret_cast<uint4*>(&Qs[ph]) = Qgv[(size_t)row * 16 + idx];
    }

    float o[8][4];
    float sacc[8][4];
    float mrun[2] = {-1e30f, -1e30f}, lrun[2] = {0.f, 0.f};
#pragma unroll
    for (int nt = 0; nt < 8; ++nt)
#pragma unroll
        for (int c = 0; c < 4; ++c) o[nt][c] = 0.f;

    const uint4* Kgv = reinterpret_cast<const uint4*>(Kg + (size_t)bh * SEQ * HDIM);
    const uint4* Vgv = reinterpret_cast<const uint4*>(Vg + (size_t)bh * HDIM * SEQ);

    for (int kt = 0; kt < SEQ / 64; ++kt) {
        const int k0 = kt * 64;
        // K rows = key (d contiguous); V rows = d (key contiguous)
#pragma unroll
        for (int i = 0; i < 4; ++i) {
            int v = tid + i * 256;
            int row = v >> 4, idx = v & 15;
            uint32_t ph = row * 64 + ((idx >> 3) << 5) + (((idx & 7) ^ (row & 7)) << 2);
            *reinterpret_cast<uint4*>(&Ks[ph]) = Kgv[(size_t)(k0 + row) * 16 + idx];
            *reinterpret_cast<uint4*>(&Vs[ph]) = Vgv[(size_t)row * (SEQ / 4) + (k0 >> 2) + idx];
        }
        __syncthreads();

        // S = Q K^T  (A=Q rows, B=K col-major via [key][d])
#pragma unroll
        for (int nt = 0; nt < 8; ++nt)
#pragma unroll
            for (int c = 0; c < 4; ++c) sacc[nt][c] = 0.f;

        const int qrow = w * 16 + g;
#pragma unroll
        for (int ks = 0; ks < 8; ++ks) {
            const int half = (ks >> 2) << 5;
            const int c0 = ((2 * (ks & 3)) ^ g) << 2;
            const int c1 = ((2 * (ks & 3) + 1) ^ g) << 2;
            uint32_t a[4];
            a[0] = Qs[qrow * 64 + half + c0 + j];
            a[2] = Qs[qrow * 64 + half + c1 + j];
            a[1] = Qs[(qrow + 8) * 64 + half + c0 + j];
            a[3] = Qs[(qrow + 8) * 64 + half + c1 + j];
#pragma unroll
            for (int nt = 0; nt < 8; ++nt) {
                int n = nt * 8 + g;
                uint32_t b0 = Ks[n * 64 + half + c0 + j];
                uint32_t b1 = Ks[n * 64 + half + c1 + j];
                mma8(sacc[nt], a, b0, b1);
            }
        }

        // online softmax (per row; row r=0 -> c0/c1, r=1 -> c2/c3)
#pragma unroll
        for (int r = 0; r < 2; ++r) {
            const int q = q0 + w * 16 + g + r * 8;
            float vv[8][2];
            int mk[8][2];
            float rowm = mrun[r];
#pragma unroll
            for (int nt = 0; nt < 8; ++nt) {
                float2 ad = *reinterpret_cast<const float2*>(&adj[(size_t)q * SEQ + k0 + nt * 8 + 2 * j]);
                int2 mm = *reinterpret_cast<const int2*>(&mask[((size_t)b * SEQ + q) * SEQ + k0 + nt * 8 + 2 * j]);
                float s0 = sacc[nt][r * 2 + 0] + ad.x;
                float s1 = sacc[nt][r * 2 + 1] + ad.y;
                vv[nt][0] = s0; vv[nt][1] = s1;
                mk[nt][0] = mm.x; mk[nt][1] = mm.y;
                if (mm.x) rowm = fmaxf(rowm, s0);
                if (mm.y) rowm = fmaxf(rowm, s1);
            }
            rowm = fmaxf(rowm, __shfl_xor_sync(0xffffffffu, rowm, 1));
            rowm = fmaxf(rowm, __shfl_xor_sync(0xffffffffu, rowm, 2));

            float rs = 0.f;
            const int prow = w * 16 + g + r * 8;
#pragma unroll
            for (int nt = 0; nt < 8; ++nt) {
                float p0 = mk[nt][0] ? __expf(vv[nt][0] - rowm) : 0.f;
                float p1 = mk[nt][1] ? __expf(vv[nt][1] - rowm) : 0.f;
                rs += p0 + p1;
                uint32_t ph = prow * 64 + ((nt >> 2) << 5) +
                              (((2 * (nt & 3) + (j >> 1)) ^ g) << 2) + 2 * (j & 1);
                *reinterpret_cast<uint2*>(&Ps[ph]) = make_uint2(f2tf(p0), f2tf(p1));
            }
            rs += __shfl_xor_sync(0xffffffffu, rs, 1);
            rs += __shfl_xor_sync(0xffffffffu, rs, 2);
            float al = __expf(mrun[r] - rowm);
            mrun[r] = rowm;
            lrun[r] = lrun[r] * al + rs;
#pragma unroll
            for (int nt = 0; nt < 8; ++nt) { o[nt][r * 2] *= al; o[nt][r * 2 + 1] *= al; }
        }
        __syncwarp();   // Ps is per-warp private (rows w*16..w*16+15)

        // O += P V   (A=P rows, B=V col-major via [d][key])
#pragma unroll
        for (int ks = 0; ks < 8; ++ks) {
            const int half = (ks >> 2) << 5;
            const int c0 = ((2 * (ks & 3)) ^ g) << 2;
            const int c1 = ((2 * (ks & 3) + 1) ^ g) << 2;
            uint32_t a[4];
            a[0] = Ps[qrow * 64 + half + c0 + j];
            a[2] = Ps[qrow * 64 + half + c1 + j];
            a[1] = Ps[(qrow + 8) * 64 + half + c0 + j];
            a[3] = Ps[(qrow + 8) * 64 + half + c1 + j];
#pragma unroll
            for (int nt = 0; nt < 8; ++nt) {
                int d = nt * 8 + g;
                uint32_t b0 = Vs[d * 64 + half + c0 + j];
                uint32_t b1 = Vs[d * 64 + half + c1 + j];
                mma8(o[nt], a, b0, b1);
            }
        }
        __syncthreads();   // protect Ks/Vs for next iter
    }

    // normalize + write fp32 to g_attn [b][s][h*64+d]
    const float inv0 = 1.f / lrun[0];
    const float inv1 = 1.f / lrun[1];
    const int qa = q0 + w * 16 + g;
#pragma unroll
    for (int nt = 0; nt < 8; ++nt) {
        int dcol = h * HDIM + nt * 8 + 2 * j;
        *reinterpret_cast<float2*>(&outp[((size_t)b * SEQ + qa) * EMB + dcol]) =
            make_float2(o[nt][0] * inv0, o[nt][1] * inv0);
        *reinterpret_cast<float2*>(&outp[((size_t)b * SEQ + qa + 8) * EMB + dcol]) =
            make_float2(o[nt][2] * inv1, o[nt][3] * inv1);
    }
}

// ---------------- launch ---------------------------------------------------
extern "C" void kernel_launch(void* const* d_in, const int* in_sizes, int n_in,
                              void* d_out, int out_size)
{
    const float* query = (const float*)d_in[0];
    const float* key   = (const float*)d_in[1];
    const float* value = (const float*)d_in[2];
    const float* adj   = (const float*)d_in[3];
    const int*   mask  = (const int*)d_in[4];
    const float* Wq = (const float*)d_in[5];
    const float* bq = (const float*)d_in[6];
    const float* Wk = (const float*)d_in[7];
    const float* bk = (const float*)d_in[8];
    const float* Wv = (const float*)d_in[9];
    const float* bv = (const float*)d_in[10];
    const float* Wo = (const float*)d_in[11];
    const float* bo = (const float*)d_in[12];
    float* out = (float*)d_out;

    float *gq, *gk, *gv, *ga;
    cudaGetSymbolAddress((void**)&gq, g_q);
    cudaGetSymbolAddress((void**)&gk, g_k);
    cudaGetSymbolAddress((void**)&gv, g_v);
    cudaGetSymbolAddress((void**)&ga, g_attn);

    cudaFuncSetAttribute(attn_tf32, cudaFuncAttributeMaxDynamicSharedMemorySize, ATTN_SMEM);

    dim3 ggrid(EMB / 128, ROWS / 128);   // (8, 32)
    gemm_tf32<<<ggrid, 128>>>(query, Wq, bq, gq, 2, 0.125f);  // Q pre-scaled 1/sqrt(64)
    gemm_tf32<<<ggrid, 128>>>(key,   Wk, bk, gk, 2, 1.0f);
    gemm_tf32<<<ggrid, 128>>>(value, Wv, bv, gv, 1, 1.0f);

    dim3 agrid(SEQ / 128, BH);           // (16, 32)
    attn_tf32<<<agrid, 256, ATTN_SMEM>>>(gq, gk, gv, adj, mask, ga);

    gemm_tf32<<<ggrid, 128>>>(ga, Wo, bo, out, 0, 1.0f);
}

// round 3
// speedup vs baseline: 3.0787x; 1.2147x over previous
#include <cuda_runtime.h>
#include <cstdint>

#define BATCH 2
#define SEQ   2048
#define EMB   1024
#define HEADS 16
#define HDIM  64
#define BH    (BATCH*HEADS)
#define ROWS  (BATCH*SEQ)

// ---------------- scratch ---------------------------------------------------
__device__ uint32_t g_xq[ROWS * EMB];      // tf32 bits of query
__device__ uint32_t g_xk[ROWS * EMB];
__device__ uint32_t g_xv[ROWS * EMB];
__device__ uint32_t g_wq[EMB * EMB];       // tf32 bits of weights
__device__ uint32_t g_wk[EMB * EMB];
__device__ uint32_t g_wv[EMB * EMB];
__device__ uint32_t g_wo[EMB * EMB];
__device__ uint32_t g_q[BH * SEQ * HDIM];  // [bh][s][d] tf32, pre-scaled 1/8
__device__ uint32_t g_k[BH * SEQ * HDIM];  // [bh][s][d] tf32
__device__ uint32_t g_v[BH * HDIM * SEQ];  // [bh][d][s] tf32
__device__ uint32_t g_attn[ROWS * EMB];    // tf32 bits
__device__ uint32_t g_mb[BATCH * SEQ * (SEQ / 32)];  // mask bitpacked

// ---------------- helpers ---------------------------------------------------
__device__ __forceinline__ uint32_t f2tf(float x) {
    uint32_t r;
    asm("cvt.rna.tf32.f32 %0, %1;" : "=r"(r) : "f"(x));
    return r;
}
__device__ __forceinline__ void mma8(float* d, const uint32_t* a, uint32_t b0, uint32_t b1) {
    asm volatile(
        "mma.sync.aligned.m16n8k8.row.col.f32.tf32.tf32.f32 "
        "{%0,%1,%2,%3}, {%4,%5,%6,%7}, {%8,%9}, {%0,%1,%2,%3};"
        : "+f"(d[0]), "+f"(d[1]), "+f"(d[2]), "+f"(d[3])
        : "r"(a[0]), "r"(a[1]), "r"(a[2]), "r"(a[3]), "r"(b0), "r"(b1));
}
__device__ __forceinline__ void ldsm4(uint32_t* r, uint32_t addr) {
    asm volatile("ldmatrix.sync.aligned.m8n8.x4.shared.b16 {%0,%1,%2,%3}, [%4];"
                 : "=r"(r[0]), "=r"(r[1]), "=r"(r[2]), "=r"(r[3]) : "r"(addr));
}
__device__ __forceinline__ void cpa16(uint32_t dst, const void* src) {
    asm volatile("cp.async.cg.shared.global [%0], [%1], 16;" :: "r"(dst), "l"(src));
}
__device__ __forceinline__ void cp_commit() { asm volatile("cp.async.commit_group;"); }
template<int N> __device__ __forceinline__ void cp_wait() {
    asm volatile("cp.async.wait_group %0;" :: "n"(N));
}

// ---------------- pre-pass kernels ------------------------------------------
__global__ void cvt_tf32_k(const float4* __restrict__ s, uint4* __restrict__ d, int n4) {
    int i = blockIdx.x * 256 + threadIdx.x;
    if (i < n4) {
        float4 v = s[i];
        d[i] = make_uint4(f2tf(v.x), f2tf(v.y), f2tf(v.z), f2tf(v.w));
    }
}
__global__ void pack_mask_k(const int* __restrict__ m, uint32_t* __restrict__ o) {
    int t = blockIdx.x * 256 + threadIdx.x;
    unsigned bal = __ballot_sync(0xffffffffu, m[t] != 0);
    if ((t & 31) == 0) o[t >> 5] = bal;
}

// ---------------- GEMM: Y = (X @ W^T + b)*scale, tf32 mma, cp.async 2-stage -
// X,W pre-converted tf32 bits. 128x128x32 tile, 8 warps (2m x 4n), warp 64x32.
__global__ __launch_bounds__(256, 2) void gemm_tf32(
    const uint32_t* __restrict__ X, const uint32_t* __restrict__ W,
    const float* __restrict__ bias, uint32_t* __restrict__ Y,
    int layout, float scale)
{
    __shared__ uint32_t As[2][4096];
    __shared__ uint32_t Bs[2][4096];
    const int tid = threadIdx.x, lane = tid & 31, wid = tid >> 5;
    const int g = lane >> 2, j = lane & 3;
    const int wm = (wid & 1) * 64, wn = (wid >> 1) * 32;
    const int m0 = blockIdx.y * 128, n0 = blockIdx.x * 128;
    const uint32_t aB = (uint32_t)__cvta_generic_to_shared(&As[0][0]);
    const uint32_t bB = (uint32_t)__cvta_generic_to_shared(&Bs[0][0]);

    const int c_ = tid & 7, r_ = tid >> 3;                 // loader: col4-slot, base row
    const uint32_t swz = (uint32_t)((c_ ^ (r_ & 7)) << 2); // word offset within row

#define LOADT(buf, k0) do {                                                            \
    _Pragma("unroll")                                                                  \
    for (int i_ = 0; i_ < 4; ++i_) {                                                   \
        int row = r_ + i_ * 32;                                                        \
        uint32_t dw = (uint32_t)row * 32u + swz;                                       \
        cpa16(aB + (uint32_t)(buf) * 16384u + dw * 4u,                                 \
              X + (size_t)(m0 + row) * EMB + (k0) + c_ * 4);                           \
        cpa16(bB + (uint32_t)(buf) * 16384u + dw * 4u,                                 \
              W + (size_t)(n0 + row) * EMB + (k0) + c_ * 4);                           \
    }                                                                                  \
    cp_commit(); } while (0)

    float acc[4][4][4];
#pragma unroll
    for (int mt = 0; mt < 4; ++mt)
#pragma unroll
        for (int nt = 0; nt < 4; ++nt)
#pragma unroll
            for (int c = 0; c < 4; ++c) acc[mt][nt][c] = 0.f;

    const int sr = (lane & 7) + (((lane >> 3) & 1) << 3);  // ldmatrix sub-row 0..15
    const int e  = lane >> 4;                              // colgroup half select

    LOADT(0, 0);
    for (int kt = 0; kt < 32; ++kt) {
        const int buf = kt & 1;
        LOADT(buf ^ 1, ((kt + 1) & 31) * 32);
        cp_wait<1>();
        __syncthreads();
        const uint32_t ab = aB + (uint32_t)buf * 16384u;
        const uint32_t bb = bB + (uint32_t)buf * 16384u;
#pragma unroll
        for (int ks = 0; ks < 4; ++ks) {
            uint32_t afr[4][4];
#pragma unroll
            for (int mt = 0; mt < 4; ++mt) {
                int row = wm + mt * 16 + sr;
                ldsm4(afr[mt], ab + (uint32_t)row * 128u +
                               ((uint32_t)((ks * 2 + e) ^ (row & 7)) << 4));
            }
#pragma unroll
            for (int ntp = 0; ntp < 2; ++ntp) {
                int row = wn + ntp * 16 + sr;
                uint32_t bfr[4];
                ldsm4(bfr, bb + (uint32_t)row * 128u +
                           ((uint32_t)((ks * 2 + e) ^ (row & 7)) << 4));
#pragma unroll
                for (int mt = 0; mt < 4; ++mt) {
                    mma8(acc[mt][2 * ntp],     afr[mt], bfr[0], bfr[2]);
                    mma8(acc[mt][2 * ntp + 1], afr[mt], bfr[1], bfr[3]);
                }
            }
        }
        __syncthreads();
    }
#undef LOADT

    // epilogue
#pragma unroll
    for (int nt = 0; nt < 4; ++nt) {
        int n = n0 + wn + nt * 8 + 2 * j;
        float2 bb2 = *reinterpret_cast<const float2*>(&bias[n]);
#pragma unroll
        for (int mt = 0; mt < 4; ++mt) {
            int m = m0 + wm + mt * 16 + g;
            float v00 = (acc[mt][nt][0] + bb2.x) * scale;
            float v01 = (acc[mt][nt][1] + bb2.y) * scale;
            float v10 = (acc[mt][nt][2] + bb2.x) * scale;
            float v11 = (acc[mt][nt][3] + bb2.y) * scale;
            if (layout == 0) {
                *reinterpret_cast<uint2*>(&Y[(size_t)m * EMB + n]) =
                    make_uint2(__float_as_uint(v00), __float_as_uint(v01));
                *reinterpret_cast<uint2*>(&Y[(size_t)(m + 8) * EMB + n]) =
                    make_uint2(__float_as_uint(v10), __float_as_uint(v11));
            } else {
                int bI = m >> 11, s = m & 2047, hh = n >> 6, d = n & 63;
                if (layout == 2) {  // [bh][s][d]
                    size_t base = ((size_t)(bI * HEADS + hh) * SEQ + s) * HDIM + d;
                    *reinterpret_cast<uint2*>(&Y[base]) = make_uint2(f2tf(v00), f2tf(v01));
                    *reinterpret_cast<uint2*>(&Y[base + 8 * HDIM]) =
                        make_uint2(f2tf(v10), f2tf(v11));
                } else {            // layout 1: [bh][d][s]
                    size_t base = ((size_t)(bI * HEADS + hh) * HDIM + d) * SEQ + s;
                    Y[base]           = f2tf(v00);
                    Y[base + SEQ]     = f2tf(v01);
                    Y[base + 8]       = f2tf(v10);
                    Y[base + SEQ + 8] = f2tf(v11);
                }
            }
        }
    }
}

// ---------------- flash attention -------------------------------------------
// smem words: Qs[128][64] @0, Ks[2][64][64] @8192, Vs[64][64] @16384, Ps[128][64] @20480
#define QS_OFF 0u
#define KS_OFF 8192u
#define VS_OFF 16384u
#define PS_OFF 20480u
#define ATTN_SMEM (28672 * 4)

__global__ __launch_bounds__(256, 2) void attn_tf32(
    const uint32_t* __restrict__ Qg, const uint32_t* __restrict__ Kg,
    const uint32_t* __restrict__ Vg, const float* __restrict__ adj,
    const uint32_t* __restrict__ mb, uint32_t* __restrict__ outp)
{
    extern __shared__ uint32_t sw[];
    const uint32_t sb = (uint32_t)__cvta_generic_to_shared(sw);
    const int tid = threadIdx.x, lane = tid & 31, w = tid >> 5;
    const int g = lane >> 2, j = lane & 3;
    const int bh = blockIdx.y, b = bh >> 4, h = bh & 15;
    const int q0 = blockIdx.x * 128;

    const int r_ = tid >> 4, i_ = tid & 15;  // loader: base row, float4 idx
    const uint32_t ldC = ((uint32_t)(i_ >> 3) << 5) + ((uint32_t)((i_ & 7) ^ (r_ & 7)) << 2);

    // prologue group: Q tile + K[0]
#pragma unroll
    for (int i = 0; i < 8; ++i) {
        int row = r_ + i * 16;
        cpa16(sb + (QS_OFF + (uint32_t)row * 64u + ldC) * 4u,
              Qg + ((size_t)bh * SEQ + q0 + row) * HDIM + i_ * 4);
    }
#pragma unroll
    for (int i = 0; i < 4; ++i) {
        int row = r_ + i * 16;
        cpa16(sb + (KS_OFF + (uint32_t)row * 64u + ldC) * 4u,
              Kg + ((size_t)bh * SEQ + row) * HDIM + i_ * 4);
    }
    cp_commit();

    float o[8][4];
    float mrun[2] = {-1e30f, -1e30f}, lrun[2] = {0.f, 0.f};
#pragma unroll
    for (int nt = 0; nt < 8; ++nt)
#pragma unroll
        for (int c = 0; c < 4; ++c) o[nt][c] = 0.f;

    const int sr   = (lane & 7) + (((lane >> 3) & 1) << 3);
    const int e    = lane >> 4;
    const int arow = w * 16 + sr;
    const uint32_t qab = sb + (QS_OFF + (uint32_t)arow * 64u) * 4u;
    const uint32_t pab = sb + (PS_OFF + (uint32_t)arow * 64u) * 4u;

    for (int kt = 0; kt < 32; ++kt) {
        const int k0 = kt * 64, buf = kt & 1;

        // (a) V[kt] -> Vs (free: prev PV done + barrier)
#pragma unroll
        for (int i = 0; i < 4; ++i) {
            int row = r_ + i * 16;
            cpa16(sb + (VS_OFF + (uint32_t)row * 64u + ldC) * 4u,
                  Vg + ((size_t)bh * HDIM + row) * SEQ + k0 + i_ * 4);
        }
        cp_commit();
        // (b) K[kt+1] -> Ks[buf^1] (redundant wrap on last iter keeps counts uniform)
        {
            int kn = ((kt + 1) & 31) * 64;
#pragma unroll
            for (int i = 0; i < 4; ++i) {
                int row = r_ + i * 16;
                cpa16(sb + (KS_OFF + (uint32_t)(buf ^ 1) * 4096u + (uint32_t)row * 64u + ldC) * 4u,
                      Kg + ((size_t)bh * SEQ + kn + row) * HDIM + i_ * 4);
            }
            cp_commit();
        }
        cp_wait<2>();        // K[kt] (and Q on kt=0) complete
        __syncthreads();

        // ---- S = Q K^T ----
        float sacc[8][4];
#pragma unroll
        for (int nt = 0; nt < 8; ++nt)
#pragma unroll
            for (int c = 0; c < 4; ++c) sacc[nt][c] = 0.f;

        const uint32_t kb = sb + (KS_OFF + (uint32_t)buf * 4096u) * 4u;
#pragma unroll
        for (int ks = 0; ks < 8; ++ks) {
            const uint32_t coff = ((uint32_t)(ks >> 2) << 7);
            uint32_t a[4];
            ldsm4(a, qab + coff + ((uint32_t)(((ks & 3) * 2 + e) ^ (arow & 7)) << 4));
#pragma unroll
            for (int ntp = 0; ntp < 4; ++ntp) {
                int row = ntp * 16 + sr;
                uint32_t bf[4];
                ldsm4(bf, kb + (uint32_t)row * 256u + coff +
                          ((uint32_t)(((ks & 3) * 2 + e) ^ (row & 7)) << 4));
                mma8(sacc[2 * ntp],     a, bf[0], bf[2]);
                mma8(sacc[2 * ntp + 1], a, bf[1], bf[3]);
            }
        }

        // ---- online softmax ----
#pragma unroll
        for (int r = 0; r < 2; ++r) {
            const int q = q0 + w * 16 + g + r * 8;
            const uint2 mw = *reinterpret_cast<const uint2*>(
                &mb[(((size_t)b * SEQ + q) << 6) + (kt << 1)]);
            float rowm = mrun[r];
            float vv[8][2];
            uint32_t mk[8];
#pragma unroll
            for (int nt = 0; nt < 8; ++nt) {
                float2 ad = *reinterpret_cast<const float2*>(
                    &adj[(size_t)q * SEQ + k0 + nt * 8 + 2 * j]);
                uint32_t u = ((nt < 4) ? mw.x : mw.y) >> ((nt * 8 + 2 * j) & 31);
                float s0 = sacc[nt][r * 2]     + ad.x;
                float s1 = sacc[nt][r * 2 + 1] + ad.y;
                vv[nt][0] = s0; vv[nt][1] = s1; mk[nt] = u & 3u;
                rowm = fmaxf(rowm, (u & 1u) ? s0 : -1e30f);
                rowm = fmaxf(rowm, (u & 2u) ? s1 : -1e30f);
            }
            rowm = fmaxf(rowm, __shfl_xor_sync(0xffffffffu, rowm, 1));
            rowm = fmaxf(rowm, __shfl_xor_sync(0xffffffffu, rowm, 2));
            float rs = 0.f;
            const int prow = w * 16 + g + r * 8;
#pragma unroll
            for (int nt = 0; nt < 8; ++nt) {
                float p0 = (mk[nt] & 1u) ? __expf(vv[nt][0] - rowm) : 0.f;
                float p1 = (mk[nt] & 2u) ? __expf(vv[nt][1] - rowm) : 0.f;
                rs += p0 + p1;
                uint32_t ph = (uint32_t)(PS_OFF + prow * 64 + ((nt >> 2) << 5) +
                                         ((((nt & 3) * 2 + (j >> 1)) ^ (prow & 7)) << 2) +
                                         (j & 1) * 2);
                *reinterpret_cast<uint2*>(&sw[ph]) = make_uint2(f2tf(p0), f2tf(p1));
            }
            rs += __shfl_xor_sync(0xffffffffu, rs, 1);
            rs += __shfl_xor_sync(0xffffffffu, rs, 2);
            float al = __expf(mrun[r] - rowm);
            mrun[r] = rowm;
            lrun[r] = lrun[r] * al + rs;
#pragma unroll
            for (int nt = 0; nt < 8; ++nt) { o[nt][2 * r] *= al; o[nt][2 * r + 1] *= al; }
        }
        __syncwarp();
        cp_wait<1>();        // V[kt] complete (hidden under QK+softmax)
        __syncthreads();

        // ---- O += P V ----
#pragma unroll
        for (int ks = 0; ks < 8; ++ks) {
            const uint32_t coff = ((uint32_t)(ks >> 2) << 7);
            uint32_t a[4];
            ldsm4(a, pab + coff + ((uint32_t)(((ks & 3) * 2 + e) ^ (arow & 7)) << 4));
#pragma unroll
            for (int ntp = 0; ntp < 4; ++ntp) {
                int row = ntp * 16 + sr;
                uint32_t bf[4];
                ldsm4(bf, sb + VS_OFF * 4u + (uint32_t)row * 256u + coff +
                          ((uint32_t)(((ks & 3) * 2 + e) ^ (row & 7)) << 4));
                mma8(o[2 * ntp],     a, bf[0], bf[2]);
                mma8(o[2 * ntp + 1], a, bf[1], bf[3]);
            }
        }
        __syncthreads();     // Vs/Ks[buf] free for next iter's cp.async
    }

    // epilogue: write tf32 bits to g_attn [b][s][h*64+d]
    const float inv0 = 1.f / lrun[0], inv1 = 1.f / lrun[1];
    const int qa = q0 + w * 16 + g;
#pragma unroll
    for (int nt = 0; nt < 8; ++nt) {
        int dcol = h * HDIM + nt * 8 + 2 * j;
        *reinterpret_cast<uint2*>(&outp[((size_t)b * SEQ + qa) * EMB + dcol]) =
            make_uint2(f2tf(o[nt][0] * inv0), f2tf(o[nt][1] * inv0));
        *reinterpret_cast<uint2*>(&outp[((size_t)b * SEQ + qa + 8) * EMB + dcol]) =
            make_uint2(f2tf(o[nt][2] * inv1), f2tf(o[nt][3] * inv1));
    }
}

// ---------------- launch -----------------------------------------------------
extern "C" void kernel_launch(void* const* d_in, const int* in_sizes, int n_in,
                              void* d_out, int out_size)
{
    const float* query = (const float*)d_in[0];
    const float* key   = (const float*)d_in[1];
    const float* value = (const float*)d_in[2];
    const float* adj   = (const float*)d_in[3];
    const int*   mask  = (const int*)d_in[4];
    const float* Wq = (const float*)d_in[5];
    const float* bq = (const float*)d_in[6];
    const float* Wk = (const float*)d_in[7];
    const float* bk = (const float*)d_in[8];
    const float* Wv = (const float*)d_in[9];
    const float* bv = (const float*)d_in[10];
    const float* Wo = (const float*)d_in[11];
    const float* bo = (const float*)d_in[12];

    uint32_t *xq, *xk, *xv, *wq, *wk, *wv, *wo, *qq, *kk, *vv, *at, *mbp;
    cudaGetSymbolAddress((void**)&xq, g_xq);
    cudaGetSymbolAddress((void**)&xk, g_xk);
    cudaGetSymbolAddress((void**)&xv, g_xv);
    cudaGetSymbolAddress((void**)&wq, g_wq);
    cudaGetSymbolAddress((void**)&wk, g_wk);
    cudaGetSymbolAddress((void**)&wv, g_wv);
    cudaGetSymbolAddress((void**)&wo, g_wo);
    cudaGetSymbolAddress((void**)&qq, g_q);
    cudaGetSymbolAddress((void**)&kk, g_k);
    cudaGetSymbolAddress((void**)&vv, g_v);
    cudaGetSymbolAddress((void**)&at, g_attn);
    cudaGetSymbolAddress((void**)&mbp, g_mb);

    cudaFuncSetAttribute(attn_tf32, cudaFuncAttributeMaxDynamicSharedMemorySize, ATTN_SMEM);

    // pre-pass: tf32 conversion + mask bitpack
    cvt_tf32_k<<<(ROWS * EMB / 4) / 256, 256>>>((const float4*)query, (uint4*)xq, ROWS * EMB / 4);
    cvt_tf32_k<<<(ROWS * EMB / 4) / 256, 256>>>((const float4*)key,   (uint4*)xk, ROWS * EMB / 4);
    cvt_tf32_k<<<(ROWS * EMB / 4) / 256, 256>>>((const float4*)value, (uint4*)xv, ROWS * EMB / 4);
    cvt_tf32_k<<<(EMB * EMB / 4) / 256, 256>>>((const float4*)Wq, (uint4*)wq, EMB * EMB / 4);
    cvt_tf32_k<<<(EMB * EMB / 4) / 256, 256>>>((const float4*)Wk, (uint4*)wk, EMB * EMB / 4);
    cvt_tf32_k<<<(EMB * EMB / 4) / 256, 256>>>((const float4*)Wv, (uint4*)wv, EMB * EMB / 4);
    cvt_tf32_k<<<(EMB * EMB / 4) / 256, 256>>>((const float4*)Wo, (uint4*)wo, EMB * EMB / 4);
    pack_mask_k<<<(BATCH * SEQ * SEQ) / 256, 256>>>(mask, mbp);

    dim3 gg(EMB / 128, ROWS / 128);   // (8, 32)
    gemm_tf32<<<gg, 256>>>(xq, wq, bq, qq, 2, 0.125f);
    gemm_tf32<<<gg, 256>>>(xk, wk, bk, kk, 2, 1.0f);
    gemm_tf32<<<gg, 256>>>(xv, wv, bv, vv, 1, 1.0f);

    dim3 ag(SEQ / 128, BH);           // (16, 32)
    attn_tf32<<<ag, 256, ATTN_SMEM>>>(qq, kk, vv, adj, mbp, at);

    gemm_tf32<<<gg, 256>>>(at, wo, bo, (uint32_t*)d_out, 0, 1.0f);
}

// round 5
// speedup vs baseline: 4.9674x; 1.6135x over previous
#include <cuda_runtime.h>
#include <cuda_fp16.h>
#include <cstdint>

#define BATCH 2
#define SEQ   2048
#define EMB   1024
#define HEADS 16
#define HDIM  64
#define BH    (BATCH*HEADS)
#define ROWS  (BATCH*SEQ)

// ---------------- scratch (half) -------------------------------------------
__device__ __half g_xq[ROWS * EMB];
__device__ __half g_xk[ROWS * EMB];
__device__ __half g_xv[ROWS * EMB];
__device__ __half g_wq[EMB * EMB];
__device__ __half g_wk[EMB * EMB];
__device__ __half g_wv[EMB * EMB];
__device__ __half g_wo[EMB * EMB];
__device__ __half g_q[BH * SEQ * HDIM];    // [bh][s][d], pre-scaled 1/8
__device__ __half g_k[BH * SEQ * HDIM];    // [bh][s][d]
__device__ __half g_v[BH * HDIM * SEQ];    // [bh][d][s]
__device__ __half g_attn[ROWS * EMB];      // [b*S+s][h*64+d]
__device__ uint32_t g_mb[BATCH * SEQ * (SEQ / 32)];

// ---------------- helpers ---------------------------------------------------
__device__ __forceinline__ void mmaH(float* d, const uint32_t* a, uint32_t b0, uint32_t b1) {
    asm volatile(
        "mma.sync.aligned.m16n8k16.row.col.f32.f16.f16.f32 "
        "{%0,%1,%2,%3}, {%4,%5,%6,%7}, {%8,%9}, {%0,%1,%2,%3};"
        : "+f"(d[0]), "+f"(d[1]), "+f"(d[2]), "+f"(d[3])
        : "r"(a[0]), "r"(a[1]), "r"(a[2]), "r"(a[3]), "r"(b0), "r"(b1));
}
__device__ __forceinline__ void ldsm4(uint32_t* r, uint32_t addr) {
    asm volatile("ldmatrix.sync.aligned.m8n8.x4.shared.b16 {%0,%1,%2,%3}, [%4];"
                 : "=r"(r[0]), "=r"(r[1]), "=r"(r[2]), "=r"(r[3]) : "r"(addr));
}
__device__ __forceinline__ void cpa16(uint32_t dst, const void* src) {
    asm volatile("cp.async.cg.shared.global [%0], [%1], 16;" :: "r"(dst), "l"(src));
}
__device__ __forceinline__ void cp_commit() { asm volatile("cp.async.commit_group;"); }
template<int N> __device__ __forceinline__ void cp_wait() {
    asm volatile("cp.async.wait_group %0;" :: "n"(N));
}

// ---------------- pre-pass ---------------------------------------------------
struct CvtBatch { const float4* s[7]; __half2* d[7]; int n4[7]; };
__global__ void cvt_batch_k(CvtBatch a) {
    const float4* s = a.s[blockIdx.y];
    __half2* d = a.d[blockIdx.y];
    int n = a.n4[blockIdx.y];
    for (int i = blockIdx.x * 256 + threadIdx.x; i < n; i += gridDim.x * 256) {
        float4 v = s[i];
        d[2 * i]     = __floats2half2_rn(v.x, v.y);
        d[2 * i + 1] = __floats2half2_rn(v.z, v.w);
    }
}
__global__ void pack_mask_k(const int* __restrict__ m, uint32_t* __restrict__ o) {
    int t = blockIdx.x * 256 + threadIdx.x;
    unsigned bal = __ballot_sync(0xffffffffu, m[t] != 0);
    if ((t & 31) == 0) o[t >> 5] = bal;
}

// ---------------- fp16 GEMM: Y = (X @ W^T + b)*scale -------------------------
// 128x128x64 tile, 256 thr (8 warps, 2m x 4n), warp 64x32, cp.async 2-stage.
// layout 0: fp32 [m][n]; 1: half [bh][d][s]; 2: half [bh][s][d]
#define GEMM_SMEM 65536

struct GemmBatch {
    const __half* X[3]; const __half* W[3]; const float* bias[3];
    void* Y[3]; int layout[3]; float scale[3];
};

__global__ __launch_bounds__(256, 2) void gemm_h(GemmBatch args)
{
    extern __shared__ __align__(1024) char smem[];
    const uint32_t sb = (uint32_t)__cvta_generic_to_shared(smem);
    const int z = blockIdx.z;
    const __half* __restrict__ X = args.X[z];
    const __half* __restrict__ W = args.W[z];
    const float* __restrict__ bias = args.bias[z];
    void* Y = args.Y[z];
    const int layout = args.layout[z];
    const float scale = args.scale[z];

    const int tid = threadIdx.x, lane = tid & 31, wid = tid >> 5;
    const int g = lane >> 2, j = lane & 3;
    const int wm = (wid & 1) * 64, wn = (wid >> 1) * 32;
    const int m0 = blockIdx.y * 128, n0 = blockIdx.x * 128;

    const int c_ = tid & 7, r_ = tid >> 3;                  // loader
    const uint32_t swz = (uint32_t)((c_ ^ (r_ & 7)) << 4);  // byte offset

    auto load_stage = [&](int c) {
        const uint32_t ab = sb + (uint32_t)(c & 1) * 16384u;
        const uint32_t bb = sb + 32768u + (uint32_t)(c & 1) * 16384u;
        const int k0 = c * 64;
#pragma unroll
        for (int i = 0; i < 4; ++i) {
            int row = r_ + i * 32;
            cpa16(ab + (uint32_t)row * 128u + swz,
                  X + (size_t)(m0 + row) * EMB + k0 + c_ * 8);
            cpa16(bb + (uint32_t)row * 128u + swz,
                  W + (size_t)(n0 + row) * EMB + k0 + c_ * 8);
        }
    };

    float acc[4][4][4];
#pragma unroll
    for (int mt = 0; mt < 4; ++mt)
#pragma unroll
        for (int nt = 0; nt < 4; ++nt)
#pragma unroll
            for (int c = 0; c < 4; ++c) acc[mt][nt][c] = 0.f;

    const int sr  = (lane & 7) + (((lane >> 3) & 1) << 3);  // A sub-row
    const int e   = lane >> 4;                               // A chunk half
    const int sbr = (lane & 7) + ((lane >> 4) << 3);         // B sub-row
    const int eb  = (lane >> 3) & 1;                         // B chunk half

    load_stage(0); cp_commit();
    for (int kt = 0; kt < 16; ++kt) {
        const int buf = kt & 1;
        if (kt + 1 < 16) load_stage(kt + 1);
        cp_commit();
        cp_wait<1>();
        __syncthreads();
        const uint32_t ab = sb + (uint32_t)buf * 16384u;
        const uint32_t bb = sb + 32768u + (uint32_t)buf * 16384u;
#pragma unroll
        for (int ks = 0; ks < 4; ++ks) {
            uint32_t afr[4][4];
#pragma unroll
            for (int mt = 0; mt < 4; ++mt) {
                int row = wm + mt * 16 + sr;
                ldsm4(afr[mt], ab + (uint32_t)row * 128u +
                               ((uint32_t)((ks * 2 + e) ^ (row & 7)) << 4));
            }
#pragma unroll
            for (int ntp = 0; ntp < 2; ++ntp) {
                int row = wn + ntp * 16 + sbr;
                uint32_t bfr[4];
                ldsm4(bfr, bb + (uint32_t)row * 128u +
                           ((uint32_t)((ks * 2 + eb) ^ (row & 7)) << 4));
#pragma unroll
                for (int mt = 0; mt < 4; ++mt) {
                    mmaH(acc[mt][2 * ntp],     afr[mt], bfr[0], bfr[1]);
                    mmaH(acc[mt][2 * ntp + 1], afr[mt], bfr[2], bfr[3]);
                }
            }
        }
        __syncthreads();
    }

    // epilogue
#pragma unroll
    for (int nt = 0; nt < 4; ++nt) {
        int n = n0 + wn + nt * 8 + 2 * j;
        float2 bb2 = *reinterpret_cast<const float2*>(&bias[n]);
#pragma unroll
        for (int mt = 0; mt < 4; ++mt) {
            int m = m0 + wm + mt * 16 + g;
            float v00 = (acc[mt][nt][0] + bb2.x) * scale;
            float v01 = (acc[mt][nt][1] + bb2.y) * scale;
            float v10 = (acc[mt][nt][2] + bb2.x) * scale;
            float v11 = (acc[mt][nt][3] + bb2.y) * scale;
            if (layout == 0) {
                float* Yf = (float*)Y;
                *reinterpret_cast<float2*>(&Yf[(size_t)m * EMB + n]) = make_float2(v00, v01);
                *reinterpret_cast<float2*>(&Yf[(size_t)(m + 8) * EMB + n]) = make_float2(v10, v11);
            } else {
                __half* Yh = (__half*)Y;
                int bI = m >> 11, s = m & 2047, h = n >> 6, d = n & 63;
                if (layout == 2) {  // [bh][s][d]
                    size_t base = ((size_t)(bI * HEADS + h) * SEQ + s) * HDIM + d;
                    *reinterpret_cast<__half2*>(&Yh[base]) = __floats2half2_rn(v00, v01);
                    *reinterpret_cast<__half2*>(&Yh[base + 8 * HDIM]) = __floats2half2_rn(v10, v11);
                } else {            // layout 1: [bh][d][s]
                    size_t base = ((size_t)(bI * HEADS + h) * HDIM + d) * SEQ + s;
                    Yh[base]           = __float2half_rn(v00);
                    Yh[base + SEQ]     = __float2half_rn(v01);
                    Yh[base + 8]       = __float2half_rn(v10);
                    Yh[base + SEQ + 8] = __float2half_rn(v11);
                }
            }
        }
    }
}

// ---------------- flash attention, fp16 mma ---------------------------------
// byte offsets: Q[128][64h]=16384 @0, K[2][64][64h] @16384, V @32768, P @40960
#define QS_B 0u
#define KS_B 16384u
#define VS_B 32768u
#define PS_B 40960u
#define ATTN_SMEM 57344

__global__ __launch_bounds__(256, 2) void attn_h(
    const __half* __restrict__ Qg, const __half* __restrict__ Kg,
    const __half* __restrict__ Vg, const float* __restrict__ adj,
    const uint32_t* __restrict__ mb, __half* __restrict__ outp)
{
    extern __shared__ __align__(1024) char sm8[];
    const uint32_t sb = (uint32_t)__cvta_generic_to_shared(sm8);
    const int tid = threadIdx.x, lane = tid & 31, w = tid >> 5;
    const int g = lane >> 2, j = lane & 3;
    const int bh = blockIdx.y, b = bh >> 4, h = bh & 15;
    const int q0 = blockIdx.x * 128;

    const int c_ = tid & 7, r_ = tid >> 3;
    const uint32_t swz = (uint32_t)((c_ ^ (r_ & 7)) << 4);

    // prologue: Q (128 rows) + K[0] (64 rows)
#pragma unroll
    for (int i = 0; i < 4; ++i) {
        int row = r_ + i * 32;
        cpa16(sb + QS_B + (uint32_t)row * 128u + swz,
              Qg + ((size_t)bh * SEQ + q0 + row) * HDIM + c_ * 8);
    }
#pragma unroll
    for (int i = 0; i < 2; ++i) {
        int row = r_ + i * 32;
        cpa16(sb + KS_B + (uint32_t)row * 128u + swz,
              Kg + ((size_t)bh * SEQ + row) * HDIM + c_ * 8);
    }
    cp_commit();

    float o[8][4];
    float mrun[2] = {-1e30f, -1e30f}, lrun[2] = {0.f, 0.f};
#pragma unroll
    for (int nt = 0; nt < 8; ++nt)
#pragma unroll
        for (int c = 0; c < 4; ++c) o[nt][c] = 0.f;

    const int sr  = (lane & 7) + (((lane >> 3) & 1) << 3);
    const int e   = lane >> 4;
    const int sbr = (lane & 7) + ((lane >> 4) << 3);
    const int eb  = (lane >> 3) & 1;
    const int arow = w * 16 + sr;
    const uint32_t qab = sb + QS_B + (uint32_t)arow * 128u;
    const uint32_t pab = sb + PS_B + (uint32_t)arow * 128u;

    for (int kt = 0; kt < 32; ++kt) {
        const int k0 = kt * 64, buf = kt & 1;
        // V[kt]
#pragma unroll
        for (int i = 0; i < 2; ++i) {
            int row = r_ + i * 32;
            cpa16(sb + VS_B + (uint32_t)row * 128u + swz,
                  Vg + ((size_t)bh * HDIM + row) * SEQ + k0 + c_ * 8);
        }
        cp_commit();
        // K[kt+1]
        {
            int kn = ((kt + 1) & 31) * 64;
#pragma unroll
            for (int i = 0; i < 2; ++i) {
                int row = r_ + i * 32;
                cpa16(sb + KS_B + (uint32_t)(buf ^ 1) * 8192u + (uint32_t)row * 128u + swz,
                      Kg + ((size_t)bh * SEQ + kn + row) * HDIM + c_ * 8);
            }
            cp_commit();
        }
        cp_wait<2>();
        __syncthreads();

        // ---- S = Q K^T ----
        float sacc[8][4];
#pragma unroll
        for (int nt = 0; nt < 8; ++nt)
#pragma unroll
            for (int c = 0; c < 4; ++c) sacc[nt][c] = 0.f;

        const uint32_t kb = sb + KS_B + (uint32_t)buf * 8192u;
#pragma unroll
        for (int ks = 0; ks < 4; ++ks) {
            uint32_t a[4];
            ldsm4(a, qab + ((uint32_t)((ks * 2 + e) ^ (arow & 7)) << 4));
#pragma unroll
            for (int ntp = 0; ntp < 4; ++ntp) {
                int row = ntp * 16 + sbr;
                uint32_t bf[4];
                ldsm4(bf, kb + (uint32_t)row * 128u +
                          ((uint32_t)((ks * 2 + eb) ^ (row & 7)) << 4));
                mmaH(sacc[2 * ntp],     a, bf[0], bf[1]);
                mmaH(sacc[2 * ntp + 1], a, bf[2], bf[3]);
            }
        }

        // ---- online softmax (fp32) ----
#pragma unroll
        for (int r = 0; r < 2; ++r) {
            const int q = q0 + w * 16 + g + r * 8;
            const uint2 mw = *reinterpret_cast<const uint2*>(
                &mb[(((size_t)b * SEQ + q) << 6) + (kt << 1)]);
            float rowm = mrun[r];
            float vv[8][2];
            uint32_t mk[8];
#pragma unroll
            for (int nt = 0; nt < 8; ++nt) {
                float2 ad = *reinterpret_cast<const float2*>(
                    &adj[(size_t)q * SEQ + k0 + nt * 8 + 2 * j]);
                uint32_t u = ((nt < 4) ? mw.x : mw.y) >> ((nt * 8 + 2 * j) & 31);
                float s0 = sacc[nt][r * 2]     + ad.x;
                float s1 = sacc[nt][r * 2 + 1] + ad.y;
                vv[nt][0] = s0; vv[nt][1] = s1; mk[nt] = u & 3u;
                rowm = fmaxf(rowm, (u & 1u) ? s0 : -1e30f);
                rowm = fmaxf(rowm, (u & 2u) ? s1 : -1e30f);
            }
            rowm = fmaxf(rowm, __shfl_xor_sync(0xffffffffu, rowm, 1));
            rowm = fmaxf(rowm, __shfl_xor_sync(0xffffffffu, rowm, 2));
            float rs = 0.f;
            const int prow = w * 16 + g + r * 8;
#pragma unroll
            for (int nt = 0; nt < 8; ++nt) {
                float p0 = (mk[nt] & 1u) ? __expf(vv[nt][0] - rowm) : 0.f;
                float p1 = (mk[nt] & 2u) ? __expf(vv[nt][1] - rowm) : 0.f;
                rs += p0 + p1;
                // P[prow][nt*8+2j] as half2; chunk = nt, in-chunk byte = 4j
                *reinterpret_cast<__half2*>(sm8 + PS_B + prow * 128 +
                    ((nt ^ (prow & 7)) << 4) + 4 * j) = __floats2half2_rn(p0, p1);
            }
            rs += __shfl_xor_sync(0xffffffffu, rs, 1);
            rs += __shfl_xor_sync(0xffffffffu, rs, 2);
            float al = __expf(mrun[r] - rowm);
            mrun[r] = rowm;
            lrun[r] = lrun[r] * al + rs;
#pragma unroll
            for (int nt = 0; nt < 8; ++nt) { o[nt][2 * r] *= al; o[nt][2 * r + 1] *= al; }
        }
        __syncwarp();   // P rows produced+consumed within this warp
        cp_wait<1>();   // V[kt] resident (hidden under QK+softmax)
        __syncthreads();

        // ---- O += P V ----
#pragma unroll
        for (int ks = 0; ks < 4; ++ks) {
            uint32_t a[4];
            ldsm4(a, pab + ((uint32_t)((ks * 2 + e) ^ (arow & 7)) << 4));
#pragma unroll
            for (int ntp = 0; ntp < 4; ++ntp) {
                int row = ntp * 16 + sbr;
                uint32_t bf[4];
                ldsm4(bf, sb + VS_B + (uint32_t)row * 128u +
                          ((uint32_t)((ks * 2 + eb) ^ (row & 7)) << 4));
                mmaH(o[2 * ntp],     a, bf[0], bf[1]);
                mmaH(o[2 * ntp + 1], a, bf[2], bf[3]);
            }
        }
        __syncthreads();
    }

    // epilogue: half out [b][s][h*64+d]
    const float inv0 = 1.f / lrun[0], inv1 = 1.f / lrun[1];
    const int qa = q0 + w * 16 + g;
#pragma unroll
    for (int nt = 0; nt < 8; ++nt) {
        int dcol = h * HDIM + nt * 8 + 2 * j;
        *reinterpret_cast<__half2*>(&outp[((size_t)b * SEQ + qa) * EMB + dcol]) =
            __floats2half2_rn(o[nt][0] * inv0, o[nt][1] * inv0);
        *reinterpret_cast<__half2*>(&outp[((size_t)b * SEQ + qa + 8) * EMB + dcol]) =
            __floats2half2_rn(o[nt][2] * inv1, o[nt][3] * inv1);
    }
}

// ---------------- launch -----------------------------------------------------
extern "C" void kernel_launch(void* const* d_in, const int* in_sizes, int n_in,
                              void* d_out, int out_size)
{
    const float* query = (const float*)d_in[0];
    const float* key   = (const float*)d_in[1];
    const float* value = (const float*)d_in[2];
    const float* adj   = (const float*)d_in[3];
    const int*   mask  = (const int*)d_in[4];
    const float* Wq = (const float*)d_in[5];
    const float* bq = (const float*)d_in[6];
    const float* Wk = (const float*)d_in[7];
    const float* bk = (const float*)d_in[8];
    const float* Wv = (const float*)d_in[9];
    const float* bv = (const float*)d_in[10];
    const float* Wo = (const float*)d_in[11];
    const float* bo = (const float*)d_in[12];

    __half *xq, *xk, *xv, *wq, *wk, *wv, *wo, *qq, *kk, *vv, *at;
    uint32_t* mbp;
    cudaGetSymbolAddress((void**)&xq, g_xq);
    cudaGetSymbolAddress((void**)&xk, g_xk);
    cudaGetSymbolAddress((void**)&xv, g_xv);
    cudaGetSymbolAddress((void**)&wq, g_wq);
    cudaGetSymbolAddress((void**)&wk, g_wk);
    cudaGetSymbolAddress((void**)&wv, g_wv);
    cudaGetSymbolAddress((void**)&wo, g_wo);
    cudaGetSymbolAddress((void**)&qq, g_q);
    cudaGetSymbolAddress((void**)&kk, g_k);
    cudaGetSymbolAddress((void**)&vv, g_v);
    cudaGetSymbolAddress((void**)&at, g_attn);
    cudaGetSymbolAddress((void**)&mbp, g_mb);

    cudaFuncSetAttribute(attn_h, cudaFuncAttributeMaxDynamicSharedMemorySize, ATTN_SMEM);
    cudaFuncSetAttribute(gemm_h, cudaFuncAttributeMaxDynamicSharedMemorySize, GEMM_SMEM);

    CvtBatch cb;
    cb.s[0] = (const float4*)query; cb.d[0] = (__half2*)xq; cb.n4[0] = ROWS * EMB / 4;
    cb.s[1] = (const float4*)key;   cb.d[1] = (__half2*)xk; cb.n4[1] = ROWS * EMB / 4;
    cb.s[2] = (const float4*)value; cb.d[2] = (__half2*)xv; cb.n4[2] = ROWS * EMB / 4;
    cb.s[3] = (const float4*)Wq;    cb.d[3] = (__half2*)wq; cb.n4[3] = EMB * EMB / 4;
    cb.s[4] = (const float4*)Wk;    cb.d[4] = (__half2*)wk; cb.n4[4] = EMB * EMB / 4;
    cb.s[5] = (const float4*)Wv;    cb.d[5] = (__half2*)wv; cb.n4[5] = EMB * EMB / 4;
    cb.s[6] = (const float4*)Wo;    cb.d[6] = (__half2*)wo; cb.n4[6] = EMB * EMB / 4;
    cvt_batch_k<<<dim3(1024, 7), 256>>>(cb);
    pack_mask_k<<<(BATCH * SEQ * SEQ) / 256, 256>>>(mask, mbp);

    // fused QKV projections
    GemmBatch gqkv;
    gqkv.X[0] = xq; gqkv.W[0] = wq; gqkv.bias[0] = bq; gqkv.Y[0] = qq;
    gqkv.layout[0] = 2; gqkv.scale[0] = 0.125f;
    gqkv.X[1] = xk; gqkv.W[1] = wk; gqkv.bias[1] = bk; gqkv.Y[1] = kk;
    gqkv.layout[1] = 2; gqkv.scale[1] = 1.0f;
    gqkv.X[2] = xv; gqkv.W[2] = wv; gqkv.bias[2] = bv; gqkv.Y[2] = vv;
    gqkv.layout[2] = 1; gqkv.scale[2] = 1.0f;
    gemm_h<<<dim3(EMB / 128, ROWS / 128, 3), 256, GEMM_SMEM>>>(gqkv);

    attn_h<<<dim3(SEQ / 128, BH), 256, ATTN_SMEM>>>(qq, kk, vv, adj, mbp, at);

    // output projection
    GemmBatch go;
    go.X[0] = at; go.W[0] = wo; go.bias[0] = bo; go.Y[0] = d_out;
    go.layout[0] = 0; go.scale[0] = 1.0f;
    go.X[1] = at; go.W[1] = wo; go.bias[1] = bo; go.Y[1] = d_out;
    go.layout[1] = 0; go.scale[1] = 1.0f;
    go.X[2] = at; go.W[2] = wo; go.bias[2] = bo; go.Y[2] = d_out;
    go.layout[2] = 0; go.scale[2] = 1.0f;
    gemm_h<<<dim3(EMB / 128, ROWS / 128, 1), 256, GEMM_SMEM>>>(go);
}